// round 1
// baseline (speedup 1.0000x reference)
#include <cuda_runtime.h>
#include <math.h>

#define TILE 16
#define NTHREADS 128
#define NMAX 50000
#define EMAX 600000

// ---------------- device scratch (no allocations allowed) ----------------
__device__ float g_q[NMAX * 128];          // q = MLP_q(h)
__device__ float g_attn[NMAX * 128];       // segment-summed alpha*v
__device__ float g_mx[NMAX * 16];          // per-(node,head) running max
__device__ float g_den[NMAX * 16];         // per-(node,head) exp-sum
__device__ float g_scores[EMAX * 16];      // scores, then exp(scores-max) in place
__device__ float g_v[(long long)EMAX * 128]; // per-edge v (after e_w scaling)

// monotone float atomic max via signed/unsigned int tricks (init to -inf)
__device__ __forceinline__ void atomicMaxF(float* addr, float v) {
    if (v >= 0.f) atomicMax((int*)addr, __float_as_int(v));
    else          atomicMin((unsigned int*)addr, __float_as_uint(v));
}

// ---------------- tiled MLP: [TILE, KIN] -> Linear -> LN -> ReLU -> Linear -> out[TILE] per thread ----------------
// 128 threads; thread t owns output column t. in_s rows must be 16B-aligned (KIN % 4 == 0).
template <int KIN>
__device__ __forceinline__ void mlp_tile(
    const float* in_s, float* hid_s, float* mu_s, float* rs_s,
    const float* __restrict__ W1, const float* __restrict__ b1,
    const float* __restrict__ gam, const float* __restrict__ bet,
    const float* __restrict__ W2, const float* __restrict__ b2,
    float* out)
{
    const int t = threadIdx.x;
    float acc[TILE];
    const float bb1 = b1[t];
#pragma unroll
    for (int e = 0; e < TILE; e++) acc[e] = bb1;

    for (int i = 0; i < KIN; i += 4) {
        const float w0 = W1[(i + 0) * 128 + t];
        const float w1 = W1[(i + 1) * 128 + t];
        const float w2 = W1[(i + 2) * 128 + t];
        const float w3 = W1[(i + 3) * 128 + t];
#pragma unroll
        for (int e = 0; e < TILE; e++) {
            const float4 x = *(const float4*)(in_s + e * KIN + i);
            acc[e] = fmaf(x.x, w0, acc[e]);
            acc[e] = fmaf(x.y, w1, acc[e]);
            acc[e] = fmaf(x.z, w2, acc[e]);
            acc[e] = fmaf(x.w, w3, acc[e]);
        }
    }
#pragma unroll
    for (int e = 0; e < TILE; e++) hid_s[e * 128 + t] = acc[e];
    __syncthreads();

    // LayerNorm statistics: warp w handles rows w, w+4, w+8, w+12
    const int w = t >> 5, lane = t & 31;
    for (int e = w; e < TILE; e += 4) {
        float s = 0.f, s2 = 0.f;
#pragma unroll
        for (int j = 0; j < 4; j++) {
            const float v = hid_s[e * 128 + lane + j * 32];
            s += v; s2 += v * v;
        }
#pragma unroll
        for (int o = 16; o; o >>= 1) {
            s  += __shfl_down_sync(0xffffffffu, s, o);
            s2 += __shfl_down_sync(0xffffffffu, s2, o);
        }
        if (lane == 0) {
            const float mu = s * (1.f / 128.f);
            const float var = s2 * (1.f / 128.f) - mu * mu;
            mu_s[e] = mu;
            rs_s[e] = rsqrtf(var + 1e-5f);
        }
    }
    __syncthreads();

    // normalize + affine + ReLU in place
    const float gt = gam[t], bt = bet[t];
#pragma unroll
    for (int e = 0; e < TILE; e++) {
        float v = hid_s[e * 128 + t];
        v = fmaf((v - mu_s[e]) * rs_s[e], gt, bt);
        hid_s[e * 128 + t] = fmaxf(v, 0.f);
    }
    __syncthreads();

    const float bb2 = b2[t];
#pragma unroll
    for (int e = 0; e < TILE; e++) out[e] = bb2;
    for (int i = 0; i < 128; i += 4) {
        const float w0 = W2[(i + 0) * 128 + t];
        const float w1 = W2[(i + 1) * 128 + t];
        const float w2 = W2[(i + 2) * 128 + t];
        const float w3 = W2[(i + 3) * 128 + t];
#pragma unroll
        for (int e = 0; e < TILE; e++) {
            const float4 x = *(const float4*)(hid_s + e * 128 + i);
            out[e] = fmaf(x.x, w0, out[e]);
            out[e] = fmaf(x.y, w1, out[e]);
            out[e] = fmaf(x.z, w2, out[e]);
            out[e] = fmaf(x.w, w3, out[e]);
        }
    }
    __syncthreads(); // hid_s reusable by caller afterwards
}

// ---------------- kernels ----------------
__global__ void init_kernel(int n) {
    const int i = blockIdx.x * blockDim.x + threadIdx.x;
    if (i < n * 128) g_attn[i] = 0.f;
    if (i < n * 16) { g_mx[i] = __int_as_float(0xff800000); g_den[i] = 0.f; }
}

__global__ void q_kernel(const float* __restrict__ h, int n,
                         const float* W1, const float* b1, const float* gam,
                         const float* bet, const float* W2, const float* b2) {
    __shared__ __align__(16) float in_s[TILE * 128];
    __shared__ __align__(16) float hid_s[TILE * 128];
    __shared__ float mu_s[TILE], rs_s[TILE];
    const int t = threadIdx.x;
    const int n0 = blockIdx.x * TILE;
    const int ne = min(TILE, n - n0);
    for (int e = 0; e < ne; e++) in_s[e * 128 + t] = h[(n0 + e) * 128 + t];
    __syncthreads();
    float out[TILE];
    mlp_tile<128>(in_s, hid_s, mu_s, rs_s, W1, b1, gam, bet, W2, b2, out);
    for (int e = 0; e < ne; e++) g_q[(n0 + e) * 128 + t] = out[e];
}

__global__ void edge_kernel(const float* __restrict__ h,
                            const float* __restrict__ rf,
                            const float* __restrict__ ef,
                            const float* __restrict__ ew,
                            const int* __restrict__ srcI,
                            const int* __restrict__ dstI, int Ecnt,
                            const float* kW1, const float* kb1, const float* kg,
                            const float* kbe, const float* kW2, const float* kb2,
                            const float* vW1, const float* vb1, const float* vg,
                            const float* vbe, const float* vW2, const float* vb2) {
    __shared__ __align__(16) float in_s[TILE * 280];
    __shared__ __align__(16) float hid_s[TILE * 128];
    __shared__ float mu_s[TILE], rs_s[TILE];
    __shared__ int dst_s[TILE];
    __shared__ float ew_s[TILE];
    const int t = threadIdx.x;
    const int e0 = blockIdx.x * TILE;
    const int ne = min(TILE, Ecnt - e0);

    for (int e = 0; e < ne; e++) {
        const int idx = e0 + e;
        const int dd = dstI[idx], ss = srcI[idx];
        if (t == 0) { dst_s[e] = dd; ew_s[e] = ew[idx]; }
        // kv_input = [edge_feat(4), r_feat(20), h[dst](128), h[src](128)]
        for (int i = t; i < 280; i += NTHREADS) {
            float val;
            if (i < 4)        val = ef[idx * 4 + i];
            else if (i < 24)  val = rf[idx * 20 + (i - 4)];
            else if (i < 152) val = h[dd * 128 + (i - 24)];
            else              val = h[ss * 128 + (i - 152)];
            in_s[e * 280 + i] = val;
        }
    }
    __syncthreads();

    // K MLP + per-head attention scores
    float kout[TILE];
    mlp_tile<280>(in_s, hid_s, mu_s, rs_s, kW1, kb1, kg, kbe, kW2, kb2, kout);
    for (int e = 0; e < ne; e++) {
        float val = kout[e] * g_q[dst_s[e] * 128 + t];
        val += __shfl_down_sync(0xffffffffu, val, 4, 8);
        val += __shfl_down_sync(0xffffffffu, val, 2, 8);
        val += __shfl_down_sync(0xffffffffu, val, 1, 8);
        if ((t & 7) == 0) {
            const float sc = val * 0.35355339059327373f; // 1/sqrt(8)
            g_scores[(e0 + e) * 16 + (t >> 3)] = sc;
            atomicMaxF(&g_mx[dst_s[e] * 16 + (t >> 3)], sc);
        }
    }

    // V MLP (scaled by e_w)
    float vout[TILE];
    mlp_tile<280>(in_s, hid_s, mu_s, rs_s, vW1, vb1, vg, vbe, vW2, vb2, vout);
    for (int e = 0; e < ne; e++)
        g_v[(long long)(e0 + e) * 128 + t] = vout[e] * ew_s[e];
}

__global__ void softmax_kernel(const int* __restrict__ dstI, int Ecnt) {
    const int gid = blockIdx.x * blockDim.x + threadIdx.x;
    if (gid >= Ecnt * 16) return;
    const int e = gid >> 4, hh = gid & 15;
    const int node = dstI[e];
    const float exv = expf(g_scores[gid] - g_mx[node * 16 + hh]);
    g_scores[gid] = exv;
    atomicAdd(&g_den[node * 16 + hh], exv);
}

__global__ void aggregate_kernel(const int* __restrict__ dstI, int Ecnt) {
    const int gid = blockIdx.x * blockDim.x + threadIdx.x;
    if (gid >= Ecnt * 128) return;
    const int e = gid >> 7, t = gid & 127;
    const int node = dstI[e];
    const int hh = t >> 3;
    const float alpha = g_scores[e * 16 + hh] / g_den[node * 16 + hh];
    atomicAdd(&g_attn[node * 128 + t], alpha * g_v[gid]);
}

__global__ void out_kernel(const float* __restrict__ h, float* __restrict__ outp, int n,
                           const float* W1, const float* b1, const float* gam,
                           const float* bet, const float* W2, const float* b2) {
    __shared__ __align__(16) float in_s[TILE * 256];
    __shared__ __align__(16) float hid_s[TILE * 128];
    __shared__ float mu_s[TILE], rs_s[TILE];
    const int t = threadIdx.x;
    const int n0 = blockIdx.x * TILE;
    const int ne = min(TILE, n - n0);
    for (int e = 0; e < ne; e++) {
        const int node = n0 + e;
        for (int i = t; i < 256; i += NTHREADS)
            in_s[e * 256 + i] = (i < 128) ? g_attn[node * 128 + i]
                                          : h[node * 128 + (i - 128)];
    }
    __syncthreads();
    float out[TILE];
    mlp_tile<256>(in_s, hid_s, mu_s, rs_s, W1, b1, gam, bet, W2, b2, out);
    for (int e = 0; e < ne; e++) outp[(n0 + e) * 128 + t] = out[e];
}

// ---------------- launch ----------------
extern "C" void kernel_launch(void* const* d_in, const int* in_sizes, int n_in,
                              void* d_out, int out_size) {
    // Discover inputs by element count (robust to metadata ordering).
    int ih = -1, ir = -1, ief = -1, iei = -1, iew = -1, xk0 = -1;
    for (int i = 0; i < n_in; i++) {
        switch (in_sizes[i]) {
            case 6400000:  if (ih  < 0) ih  = i; break; // h [N,128]
            case 12000000: if (ir  < 0) ir  = i; break; // r_feat [E,20]
            case 2400000:  if (ief < 0) ief = i; break; // edge_feat [E,4]
            case 1200000:  if (iei < 0) iei = i; break; // edge_index [2,E]
            case 600000:   if (iew < 0) iew = i; break; // e_w [E]
            case 35840:    if (xk0 < 0) xk0 = i; break; // xk_W1 [280,128] (first)
            default: break;
        }
    }
    // MLP groups are contiguous in order xk, xv, xq, out; each = W1,b1,g,beta,W2,b2
    const int xv0 = xk0 + 6, xq0 = xk0 + 12, o0 = xk0 + 18;

    const float* h   = (const float*)d_in[ih];
    const float* rf  = (const float*)d_in[ir];
    const float* ef  = (const float*)d_in[ief];
    const float* ew  = (const float*)d_in[iew];
    const int*   ei  = (const int*)d_in[iei];
    const int N = in_sizes[ih] / 128;
    const int E = in_sizes[iew];
    const int* srcI = ei;
    const int* dstI = ei + E;

#define G(base, off) ((const float*)d_in[(base) + (off)])

    float* outp = (float*)d_out;

    // 1. init scratch
    {
        const int n_el = N * 128;
        init_kernel<<<(n_el + 255) / 256, 256>>>(N);
    }
    // 2. q = MLP_q(h)
    q_kernel<<<(N + TILE - 1) / TILE, NTHREADS>>>(
        h, N, G(xq0,0), G(xq0,1), G(xq0,2), G(xq0,3), G(xq0,4), G(xq0,5));
    // 3. per-edge k/v MLPs + scores + running max
    edge_kernel<<<(E + TILE - 1) / TILE, NTHREADS>>>(
        h, rf, ef, ew, srcI, dstI, E,
        G(xk0,0), G(xk0,1), G(xk0,2), G(xk0,3), G(xk0,4), G(xk0,5),
        G(xv0,0), G(xv0,1), G(xv0,2), G(xv0,3), G(xv0,4), G(xv0,5));
    // 4. exp + denominator
    softmax_kernel<<<(E * 16 + 255) / 256, 256>>>(dstI, E);
    // 5. alpha * v scatter-add
    {
        const long long tot = (long long)E * 128;
        aggregate_kernel<<<(int)((tot + 255) / 256), 256>>>(dstI, E);
    }
    // 6. output MLP on concat(attn, h)
    out_kernel<<<(N + TILE - 1) / TILE, NTHREADS>>>(
        h, outp, N, G(o0,0), G(o0,1), G(o0,2), G(o0,3), G(o0,4), G(o0,5));
#undef G
}